// round 2
// baseline (speedup 1.0000x reference)
#include <cuda_runtime.h>
#include <cstdint>

#define NUM_BINS 32
#define C_IN     5
#define C_HID    32
#define C_OUT    64
#define C_RED    16
#define MAXK     4
#define MAXU     100352
#define NB_MAIN  1184

__device__ int  g_cnt[MAXU];
__device__ int4 g_list[MAXU];   // 4 packed (voxel<<5 | bin) entries per pillar

// ---------------------------------------------------------------- scatter ---
__global__ void scatter_kernel(const int* __restrict__ unq_inv,
                               const int* __restrict__ coords, int N) {
    int i = blockIdx.x * blockDim.x + threadIdx.x;
    if (i >= N) return;
    int p = unq_inv[i];
    int b = coords[4 * i + 1];
    int k = atomicAdd(&g_cnt[p], 1);
    if (k < MAXK) ((int*)g_list)[p * 4 + k] = (i << 5) | (b & 31);
}

// ------------------------------------------------------------------- mask ---
__global__ void mask_kernel(const int* __restrict__ cnt, float* __restrict__ out,
                            long long base, int n) {
    int i = blockIdx.x * blockDim.x + threadIdx.x;
    if (i < n) out[base + i] = (cnt[i] >= 2) ? 1.0f : 0.0f;
}

// ------------------------------------------------------------------- main ---
// One block = 64 threads = one pillar group; thread = output channel c.
// Persistent over pillars. W2/Wc2 columns live in registers.
__global__ __launch_bounds__(64, 8)
void cbam_main(const float* __restrict__ vf,
               const int*   __restrict__ unq_cnt,
               const float* __restrict__ W1,  const float* __restrict__ b1,
               const float* __restrict__ W2,  const float* __restrict__ b2,
               const float* __restrict__ Wc1, const float* __restrict__ bc1,
               const float* __restrict__ Wc2, const float* __restrict__ bc2,
               const float* __restrict__ Wsp, const float* __restrict__ bsp,
               float* __restrict__ out, int U) {
    __shared__ __align__(16) float h_sh[MAXK][32];     // hidden per occupied bin
    __shared__ __align__(16) float avg_sh[64];
    __shared__ __align__(16) float max_sh[64];
    __shared__ float hp_sh[64];
    __shared__ __align__(16) float g_sh[16];
    __shared__ __align__(16) float Wc1T[16 * 68];      // [j][c], padded rows
    __shared__ float sig_sh[32];
    __shared__ float ssum_sh[2][8], smax_sh[2][8];
    __shared__ float bc1_sh[16], cw_sh[16];

    const int c    = threadIdx.x;
    const int lane = c & 31;
    const int warp = c >> 5;

    // ---- per-block preload (amortized over ~85 pillars) ----
    float w2col[32];
#pragma unroll
    for (int j = 0; j < 32; j++) w2col[j] = W2[j * 64 + c];
    float wc2col[16];
#pragma unroll
    for (int j = 0; j < 16; j++) wc2col[j] = Wc2[j * 64 + c];
    const float b2c  = b2[c];
    const float bc2c = bc2[c];
    float w1r[5] = {0, 0, 0, 0, 0};
    float b1c = 0.f;
    if (c < 32) {
#pragma unroll
        for (int i = 0; i < 5; i++) w1r[i] = W1[i * 32 + c];
        b1c = b1[c];
    }
    // x_empty[c] = b2[c] + sum_j relu(b1[j]) * W2[j][c]
    float xemp = b2c;
#pragma unroll
    for (int j = 0; j < 32; j++) xemp = fmaf(fmaxf(b1[j], 0.f), w2col[j], xemp);

    for (int idx = c; idx < 1024; idx += 64) {
        int j = idx & 15, cc = idx >> 4;
        Wc1T[j * 68 + cc] = Wc1[cc * 16 + j];
    }
    if (c < 16) bc1_sh[c] = bc1[c];
    if (c < 14) cw_sh[c]  = Wsp[c];
    if (c == 14) { /* bsp kept in register below */ }
    const float bspv = bsp[0];
    __syncthreads();

    const float NEG_INF = __int_as_float(0xff800000);

    for (int p = blockIdx.x; p < U; p += gridDim.x) {
        int K = unq_cnt[p];
        if (K > MAXK) K = MAXK;
        if (K < 0) K = 0;
        const int4 e4 = g_list[p];
        int ents[4] = {e4.x, e4.y, e4.z, e4.w};

        // ---- phase A: hidden layer for each occupied voxel (warp0) ----
        if (c < 32) {
            for (int k = 0; k < K; k++) {
                int v = ents[k] >> 5;
                const float* f = vf + (long long)v * 5;
                float h = b1c;
                h = fmaf(f[0], w1r[0], h);
                h = fmaf(f[1], w1r[1], h);
                h = fmaf(f[2], w1r[2], h);
                h = fmaf(f[3], w1r[3], h);
                h = fmaf(f[4], w1r[4], h);
                h_sh[k][c] = fmaxf(h, 0.f);
            }
        }
        __syncthreads();

        // ---- phase B: second layer -> x for occupied bins; avg/max stats ----
        float xo[MAXK];
#pragma unroll
        for (int k = 0; k < MAXK; k++) {
            float acc = b2c;
            if (k < K) {
                const float4* h4 = (const float4*)h_sh[k];
#pragma unroll
                for (int jj = 0; jj < 8; jj++) {
                    float4 h = h4[jj];
                    acc = fmaf(h.x, w2col[4 * jj + 0], acc);
                    acc = fmaf(h.y, w2col[4 * jj + 1], acc);
                    acc = fmaf(h.z, w2col[4 * jj + 2], acc);
                    acc = fmaf(h.w, w2col[4 * jj + 3], acc);
                }
            }
            xo[k] = acc;
        }
        float a = (float)(NUM_BINS - K) * xemp;
        float m = (K < NUM_BINS) ? xemp : NEG_INF;
#pragma unroll
        for (int k = 0; k < MAXK; k++)
            if (k < K) { a += xo[k]; m = fmaxf(m, xo[k]); }
        a *= (1.f / 32.f);
        avg_sh[c] = a;
        max_sh[c] = m;
        __syncthreads();

        // ---- phase C: channel-attention hidden layer (split partials) ----
        {
            int j = c & 15, s = (c >> 4) & 1, half = c >> 5;
            const float* vsh = s ? max_sh : avg_sh;
            const float4* v4 = (const float4*)(vsh + half * 32);
            const float4* w4 = (const float4*)(&Wc1T[j * 68 + half * 32]);
            float hp = 0.f;
#pragma unroll
            for (int q = 0; q < 8; q++) {
                float4 v = v4[q];
                float4 w = w4[q];
                hp = fmaf(v.x, w.x, hp);
                hp = fmaf(v.y, w.y, hp);
                hp = fmaf(v.z, w.z, hp);
                hp = fmaf(v.w, w.w, hp);
            }
            hp_sh[c] = hp;
        }
        __syncthreads();
        if (c < 16) {
            float ha = hp_sh[c]      + hp_sh[c + 32] + bc1_sh[c];
            float hm = hp_sh[c + 16] + hp_sh[c + 48] + bc1_sh[c];
            g_sh[c] = fmaxf(ha, 0.f) + fmaxf(hm, 0.f);
        }
        __syncthreads();

        // ---- channel attention output + scale ----
        float att;
        {
            float acc = 2.f * bc2c;
            const float4* g4 = (const float4*)g_sh;
#pragma unroll
            for (int q = 0; q < 4; q++) {
                float4 g = g4[q];
                acc = fmaf(g.x, wc2col[4 * q + 0], acc);
                acc = fmaf(g.y, wc2col[4 * q + 1], acc);
                acc = fmaf(g.z, wc2col[4 * q + 2], acc);
                acc = fmaf(g.w, wc2col[4 * q + 3], acc);
            }
            att = 1.f / (1.f + __expf(-acc));
        }
        float yk[MAXK];
#pragma unroll
        for (int k = 0; k < MAXK; k++) yk[k] = att * xo[k];
        float ye = att * xemp;

        // ---- bin statistics: sum/max over channels, per stream ----
#pragma unroll
        for (int k = 0; k < MAXK; k++) {
            if (k < K) {
                float sv = yk[k], mv = yk[k];
#pragma unroll
                for (int off = 16; off > 0; off >>= 1) {
                    sv += __shfl_xor_sync(0xffffffffu, sv, off);
                    mv = fmaxf(mv, __shfl_xor_sync(0xffffffffu, mv, off));
                }
                if (lane == 0) { ssum_sh[warp][k] = sv; smax_sh[warp][k] = mv; }
            }
        }
        {
            float sv = ye, mv = ye;
#pragma unroll
            for (int off = 16; off > 0; off >>= 1) {
                sv += __shfl_xor_sync(0xffffffffu, sv, off);
                mv = fmaxf(mv, __shfl_xor_sync(0xffffffffu, mv, off));
            }
            if (lane == 0) { ssum_sh[warp][4] = sv; smax_sh[warp][4] = mv; }
        }
        __syncthreads();

        // ---- bin attention: conv7 over bins + sigmoid (warp0, lane=bin) ----
        if (c < 32) {
            int b = c;
            float sm = (ssum_sh[0][4] + ssum_sh[1][4]) * (1.f / 64.f);
            float sx = fmaxf(smax_sh[0][4], smax_sh[1][4]);
            bool occ = false;
#pragma unroll
            for (int k = 0; k < MAXK; k++) {
                if (k < K && (ents[k] & 31) == b) {
                    sm = (ssum_sh[0][k] + ssum_sh[1][k]) * (1.f / 64.f);
                    sx = fmaxf(smax_sh[0][k], smax_sh[1][k]);
                    occ = true;
                }
            }
            float arg = bspv;
#pragma unroll
            for (int t = 0; t < 7; t++) {
                int idx = b + t - 3;
                float vm = __shfl_sync(0xffffffffu, sm, idx & 31);
                float vx = __shfl_sync(0xffffffffu, sx, idx & 31);
                bool ok = (idx >= 0) && (idx < 32);
                vm = ok ? vm : 0.f;
                vx = ok ? vx : 0.f;
                arg = fmaf(cw_sh[t], vm, arg);
                arg = fmaf(cw_sh[7 + t], vx, arg);
            }
            float sg = 1.f / (1.f + __expf(-arg));
            sig_sh[b] = sg;
            // max sigmoid over EMPTY bins
            float es = occ ? NEG_INF : sg;
#pragma unroll
            for (int off = 16; off > 0; off >>= 1)
                es = fmaxf(es, __shfl_xor_sync(0xffffffffu, es, off));
            if (lane == 0) smax_sh[0][5] = es;
        }
        __syncthreads();

        // ---- final: out[c] = max_b y[c][b] * sig[b] ----
        float r = ye * smax_sh[0][5];
#pragma unroll
        for (int k = 0; k < MAXK; k++)
            if (k < K) r = fmaxf(r, yk[k] * sig_sh[ents[k] & 31]);
        out[(long long)p * 64 + c] = r;
    }
}

// ------------------------------------------------------------------ launch --
extern "C" void kernel_launch(void* const* d_in, const int* in_sizes, int n_in,
                              void* d_out, int out_size) {
    const float* vf      = (const float*)d_in[0];
    const int*   coords  = (const int*)  d_in[1];
    const int*   unq_inv = (const int*)  d_in[3];
    const int*   unq_cnt = (const int*)  d_in[4];
    const float* W1  = (const float*)d_in[5];
    const float* b1  = (const float*)d_in[6];
    const float* W2  = (const float*)d_in[7];
    const float* b2  = (const float*)d_in[8];
    const float* Wc1 = (const float*)d_in[9];
    const float* bc1 = (const float*)d_in[10];
    const float* Wc2 = (const float*)d_in[11];
    const float* bc2 = (const float*)d_in[12];
    const float* Wsp = (const float*)d_in[13];
    const float* bsp = (const float*)d_in[14];
    float* out = (float*)d_out;

    int N = in_sizes[0] / 5;
    int U = in_sizes[2];
    if (U > MAXU) U = MAXU;

    void* cnt_ptr = nullptr;
    cudaGetSymbolAddress(&cnt_ptr, g_cnt);
    cudaMemsetAsync(cnt_ptr, 0, (size_t)U * sizeof(int));

    scatter_kernel<<<(N + 255) / 256, 256>>>(unq_inv, coords, N);

    int nb = NB_MAIN;
    if (nb > U) nb = U;
    cbam_main<<<nb, 64>>>(vf, unq_cnt, W1, b1, W2, b2, Wc1, bc1, Wc2, bc2,
                          Wsp, bsp, out, U);

    long long feat = (long long)U * 64;
    if ((long long)out_size > feat) {
        long long extra = (long long)out_size - feat;
        int n = (extra > U) ? U : (int)extra;
        mask_kernel<<<(n + 255) / 256, 256>>>(unq_cnt, out, feat, n);
    }
}

// round 4
// speedup vs baseline: 1.5413x; 1.5413x over previous
#include <cuda_runtime.h>
#include <cstdint>

#define NUM_BINS 32
#define MAXK     4
#define MAXU     100352
#define NMAXV    (2*MAXU)

typedef unsigned long long u64;

__device__ int   g_cnt[MAXU];
__device__ int4  g_list[MAXU];                 // packed (voxel<<5 | bin)
__device__ float g_x[(size_t)NMAXV * 64];      // per-voxel MLP output
__device__ float g_xemp[64];                   // MLP(0) vector

// ---------------- packed f32x2 helpers -------------------------------------
__device__ __forceinline__ u64 pk2(float lo, float hi) {
    u64 r; asm("mov.b64 %0,{%1,%2};" : "=l"(r) : "f"(lo), "f"(hi)); return r;
}
__device__ __forceinline__ u64 dup2(float v) { return pk2(v, v); }
__device__ __forceinline__ void fma2(u64 &d, u64 a, u64 b) {
    asm("fma.rn.f32x2 %0,%1,%2,%0;" : "+l"(d) : "l"(a), "l"(b));
}
__device__ __forceinline__ float2 unpk(u64 v) {
    float2 r; asm("mov.b64 {%0,%1},%2;" : "=f"(r.x), "=f"(r.y) : "l"(v)); return r;
}
union F4U { float4 f; u64 u[2]; };

__device__ __forceinline__ float sigm(float x) {
    return __fdividef(1.f, 1.f + __expf(-x));
}

// ---------------------------------------------------------------- scatter ---
__global__ void scatter_kernel(const int* __restrict__ unq_inv,
                               const int* __restrict__ coords, int N) {
    int i = blockIdx.x * blockDim.x + threadIdx.x;
    if (i >= N) return;
    int p = unq_inv[i];
    int b = coords[4 * i + 1];
    int k = atomicAdd(&g_cnt[p], 1);
    if (k < MAXK) ((int*)g_list)[p * 4 + k] = (i << 5) | (b & 31);
}

// ------------------------------------------------------------------- mask ---
__global__ void mask_kernel(const int* __restrict__ cnt, float* __restrict__ out,
                            long long base, int n) {
    int i = blockIdx.x * blockDim.x + threadIdx.x;
    if (i < n) out[base + i] = (cnt[i] >= 2) ? 1.0f : 0.0f;
}

// ------------------------------------------------------------------- xemp ---
__global__ void xemp_kernel(const float* __restrict__ b1,
                            const float* __restrict__ W2,
                            const float* __restrict__ b2) {
    int c = threadIdx.x;   // 64 threads
    float acc = b2[c];
#pragma unroll
    for (int j = 0; j < 32; j++)
        acc = fmaf(fmaxf(b1[j], 0.f), W2[j * 64 + c], acc);
    g_xemp[c] = acc;
}

// ---------------------------------------------------------- kernel A: MLP ---
// thread = voxel. hidden (32) and 64 outputs via packed f32x2.
__global__ __launch_bounds__(128, 4)
void mlp_kernel(const float* __restrict__ vf,
                const float* __restrict__ W1, const float* __restrict__ b1,
                const float* __restrict__ W2, const float* __restrict__ b2,
                int N) {
    __shared__ __align__(16) float W1s[5][32];
    __shared__ __align__(16) float b1s[32];
    __shared__ __align__(16) float W2s[32][64];
    __shared__ __align__(16) float b2s[64];
    int tid = threadIdx.x;
    for (int i = tid; i < 160; i += 128) W1s[i / 32][i % 32] = W1[i];
    if (tid < 32) b1s[tid] = b1[tid];
    for (int i = tid; i < 2048; i += 128) W2s[i >> 6][i & 63] = W2[i];
    if (tid < 64) b2s[tid] = b2[tid];
    __syncthreads();

    int v = blockIdx.x * 128 + tid;
    if (v >= N) return;

    const float* f = vf + (size_t)v * 5;
    u64 fd[5];
#pragma unroll
    for (int i = 0; i < 5; i++) fd[i] = dup2(f[i]);

    // hidden layer packed (16 x f32x2)
    u64 h2[16];
#pragma unroll
    for (int jp = 0; jp < 16; jp++) h2[jp] = *(const u64*)&b1s[2 * jp];
#pragma unroll
    for (int i = 0; i < 5; i++) {
        const u64* w1r = (const u64*)&W1s[i][0];
#pragma unroll
        for (int jp = 0; jp < 16; jp++) fma2(h2[jp], fd[i], w1r[jp]);
    }
    float hs[32];
#pragma unroll
    for (int jp = 0; jp < 16; jp++) {
        float2 t = unpk(h2[jp]);
        hs[2 * jp]     = fmaxf(t.x, 0.f);
        hs[2 * jp + 1] = fmaxf(t.y, 0.f);
    }

    // output layer: acc[32] packed f32x2 = 64 channels
    u64 acc[32];
#pragma unroll
    for (int q = 0; q < 16; q++) {
        F4U b; b.f = ((const float4*)b2s)[q];
        acc[2 * q] = b.u[0]; acc[2 * q + 1] = b.u[1];
    }
#pragma unroll 4
    for (int j = 0; j < 32; j++) {
        u64 hd = dup2(hs[j]);
        const float4* wr = (const float4*)&W2s[j][0];
#pragma unroll
        for (int q = 0; q < 16; q++) {
            F4U w; w.f = wr[q];
            fma2(acc[2 * q],     hd, w.u[0]);
            fma2(acc[2 * q + 1], hd, w.u[1]);
        }
    }
    float4* dst = (float4*)&g_x[(size_t)v * 64];
#pragma unroll
    for (int q = 0; q < 16; q++) {
        F4U o; o.u[0] = acc[2 * q]; o.u[1] = acc[2 * q + 1];
        dst[q] = o.f;
    }
}

// -------------------------------------------------- kernel B: attention -----
// thread = pillar. no barriers/shuffles; 3 channel passes + register conv.
__global__ __launch_bounds__(128, 3)
void pillar_kernel(const int* __restrict__ unq_cnt,
                   const float* __restrict__ Wc1, const float* __restrict__ bc1,
                   const float* __restrict__ Wc2, const float* __restrict__ bc2,
                   const float* __restrict__ Wsp, const float* __restrict__ bsp,
                   float* __restrict__ out, int U) {
    __shared__ __align__(16) float Wc1s[64 * 16];   // [c][j]
    __shared__ __align__(16) float Wc2s[16 * 64];   // [j][c]
    __shared__ __align__(16) float xemps[64];
    __shared__ __align__(16) float bc1s[16];
    __shared__ __align__(16) float bc22[64];        // 2*bc2
    int tid = threadIdx.x;
    for (int i = tid; i < 1024; i += 128) { Wc1s[i] = Wc1[i]; Wc2s[i] = Wc2[i]; }
    if (tid < 64) { xemps[tid] = g_xemp[tid]; bc22[tid] = 2.f * bc2[tid]; }
    if (tid < 16) bc1s[tid] = bc1[tid];
    __syncthreads();

    int p = blockIdx.x * 128 + tid;
    if (p >= U) return;

    const float NEG = __int_as_float(0xff800000);
    float wm[7], wx[7];
#pragma unroll
    for (int t = 0; t < 7; t++) { wm[t] = Wsp[t]; wx[t] = Wsp[7 + t]; }
    const float bspv = bsp[0];

    int K = unq_cnt[p];
    K = (K < 0) ? 0 : ((K > MAXK) ? MAXK : K);
    int4 e = g_list[p];
    int vs_[4] = { e.x >> 5, e.y >> 5, e.z >> 5, e.w >> 5 };
    int bs_[4] = { e.x & 31, e.y & 31, e.z & 31, e.w & 31 };
#pragma unroll
    for (int k = 0; k < 4; k++) if (k >= K) bs_[k] = -1;   // kill stale slots
    const float fK = (float)(NUM_BINS - K);

    // ---- pass 1: avg/max per channel -> catt hidden partials -------------
    u64 ap[8], aq[8];
#pragma unroll
    for (int j = 0; j < 8; j++) { ap[j] = 0ull; aq[j] = 0ull; }

#pragma unroll 2
    for (int c = 0; c < 64; c += 4) {
        float4 xe = *(const float4*)&xemps[c];
        float4 s  = make_float4(0.f, 0.f, 0.f, 0.f);
        float4 mx = xe;                         // empty bins always exist (K<32)
#pragma unroll
        for (int k = 0; k < 4; k++) if (k < K) {
            float4 xv = *(const float4*)&g_x[(size_t)vs_[k] * 64 + c];
            s.x += xv.x; s.y += xv.y; s.z += xv.z; s.w += xv.w;
            mx.x = fmaxf(mx.x, xv.x); mx.y = fmaxf(mx.y, xv.y);
            mx.z = fmaxf(mx.z, xv.z); mx.w = fmaxf(mx.w, xv.w);
        }
        float av[4] = { (s.x + fK * xe.x) * 0.03125f, (s.y + fK * xe.y) * 0.03125f,
                        (s.z + fK * xe.z) * 0.03125f, (s.w + fK * xe.w) * 0.03125f };
        float mv[4] = { mx.x, mx.y, mx.z, mx.w };
#pragma unroll
        for (int cc = 0; cc < 4; cc++) {
            u64 ad = dup2(av[cc]);
            u64 md = dup2(mv[cc]);
            const u64* wr = (const u64*)&Wc1s[(c + cc) * 16];
#pragma unroll
            for (int jp = 0; jp < 8; jp++) {
                u64 w = wr[jp];
                fma2(ap[jp], ad, w);
                fma2(aq[jp], md, w);
            }
        }
    }

    // ---- catt gate vector g[16] and packed dups --------------------------
    float g[16];
#pragma unroll
    for (int jp = 0; jp < 8; jp++) {
        float2 pp = unpk(ap[jp]);
        float2 qq = unpk(aq[jp]);
        g[2 * jp]     = fmaxf(pp.x + bc1s[2 * jp], 0.f)     + fmaxf(qq.x + bc1s[2 * jp], 0.f);
        g[2 * jp + 1] = fmaxf(pp.y + bc1s[2 * jp + 1], 0.f) + fmaxf(qq.y + bc1s[2 * jp + 1], 0.f);
    }
    u64 gd[16];
#pragma unroll
    for (int j = 0; j < 16; j++) gd[j] = dup2(g[j]);

    // ---- pass 2: channel attention + bin statistics ----------------------
    float ssum[4] = {0.f, 0.f, 0.f, 0.f};
    float smax[4] = {NEG, NEG, NEG, NEG};
    float sesum = 0.f, semax = NEG;
#pragma unroll 2
    for (int c = 0; c < 64; c += 4) {
        u64 a01 = *(const u64*)&bc22[c];
        u64 a23 = *(const u64*)&bc22[c + 2];
#pragma unroll
        for (int j = 0; j < 16; j++) {
            const u64* wr = (const u64*)&Wc2s[j * 64 + c];
            fma2(a01, gd[j], wr[0]);
            fma2(a23, gd[j], wr[1]);
        }
        float2 A = unpk(a01), B = unpk(a23);
        float att[4] = { sigm(A.x), sigm(A.y), sigm(B.x), sigm(B.y) };
        float4 xe = *(const float4*)&xemps[c];
        float y0 = att[0] * xe.x, y1 = att[1] * xe.y, y2 = att[2] * xe.z, y3 = att[3] * xe.w;
        sesum += (y0 + y1) + (y2 + y3);
        semax = fmaxf(semax, fmaxf(fmaxf(y0, y1), fmaxf(y2, y3)));
#pragma unroll
        for (int k = 0; k < 4; k++) if (k < K) {
            float4 xv = *(const float4*)&g_x[(size_t)vs_[k] * 64 + c];
            float z0 = att[0] * xv.x, z1 = att[1] * xv.y, z2 = att[2] * xv.z, z3 = att[3] * xv.w;
            ssum[k] += (z0 + z1) + (z2 + z3);
            smax[k] = fmaxf(smax[k], fmaxf(fmaxf(z0, z1), fmaxf(z2, z3)));
        }
    }

    // ---- bin attention: 7-tap conv over 32 bins, all in registers --------
    const float se_m = sesum * (1.f / 64.f);
    const float se_x = semax;
    float smv[4], sxv[4];
#pragma unroll
    for (int k = 0; k < 4; k++) { smv[k] = ssum[k] * (1.f / 64.f); sxv[k] = smax[k]; }

    float vmA[32], vxA[32];
#pragma unroll
    for (int i = 0; i < 32; i++) {
        float m = se_m, x = se_x;
#pragma unroll
        for (int k = 0; k < 4; k++) {
            bool h = (bs_[k] == i);
            m = h ? smv[k] : m;
            x = h ? sxv[k] : x;
        }
        vmA[i] = m; vxA[i] = x;
    }
    float emax = NEG, emin = -NEG;     // max & min conv arg over EMPTY bins
    float argk[4] = {0.f, 0.f, 0.f, 0.f};
#pragma unroll
    for (int b = 0; b < 32; b++) {
        float a = bspv;
#pragma unroll
        for (int t = 0; t < 7; t++) {
            int i = b + t - 3;
            if (i >= 0 && i < 32) {
                a = fmaf(wm[t], vmA[i], a);
                a = fmaf(wx[t], vxA[i], a);
            }
        }
        bool occ = false;
#pragma unroll
        for (int k = 0; k < 4; k++) {
            bool h = (bs_[k] == b);
            argk[k] = h ? a : argk[k];
            occ = occ | h;
        }
        emax = occ ? emax : fmaxf(emax, a);
        emin = occ ? emin : fminf(emin, a);
    }
    float sigk[4];
#pragma unroll
    for (int k = 0; k < 4; k++) sigk[k] = sigm(argk[k]);
    const float sigeP = sigm(emax);    // used when y_empty >= 0
    const float sigeN = sigm(emin);    // used when y_empty <  0

    // ---- pass 3: final max over bins ------------------------------------
#pragma unroll 2
    for (int c = 0; c < 64; c += 4) {
        u64 a01 = *(const u64*)&bc22[c];
        u64 a23 = *(const u64*)&bc22[c + 2];
#pragma unroll
        for (int j = 0; j < 16; j++) {
            const u64* wr = (const u64*)&Wc2s[j * 64 + c];
            fma2(a01, gd[j], wr[0]);
            fma2(a23, gd[j], wr[1]);
        }
        float2 A = unpk(a01), B = unpk(a23);
        float att[4] = { sigm(A.x), sigm(A.y), sigm(B.x), sigm(B.y) };
        float4 xe = *(const float4*)&xemps[c];
        float xec[4] = { xe.x, xe.y, xe.z, xe.w };
        float M[4];
#pragma unroll
        for (int cc = 0; cc < 4; cc++)
            M[cc] = xec[cc] * ((xec[cc] >= 0.f) ? sigeP : sigeN);
#pragma unroll
        for (int k = 0; k < 4; k++) if (k < K) {
            float4 xv = *(const float4*)&g_x[(size_t)vs_[k] * 64 + c];
            M[0] = fmaxf(M[0], xv.x * sigk[k]);
            M[1] = fmaxf(M[1], xv.y * sigk[k]);
            M[2] = fmaxf(M[2], xv.z * sigk[k]);
            M[3] = fmaxf(M[3], xv.w * sigk[k]);
        }
        float4 o = make_float4(att[0] * M[0], att[1] * M[1], att[2] * M[2], att[3] * M[3]);
        *(float4*)&out[(size_t)p * 64 + c] = o;
    }
}

// ------------------------------------------------------------------ launch --
extern "C" void kernel_launch(void* const* d_in, const int* in_sizes, int n_in,
                              void* d_out, int out_size) {
    const float* vf      = (const float*)d_in[0];
    const int*   coords  = (const int*)  d_in[1];
    const int*   unq_inv = (const int*)  d_in[3];
    const int*   unq_cnt = (const int*)  d_in[4];
    const float* W1  = (const float*)d_in[5];
    const float* b1  = (const float*)d_in[6];
    const float* W2  = (const float*)d_in[7];
    const float* b2  = (const float*)d_in[8];
    const float* Wc1 = (const float*)d_in[9];
    const float* bc1 = (const float*)d_in[10];
    const float* Wc2 = (const float*)d_in[11];
    const float* bc2 = (const float*)d_in[12];
    const float* Wsp = (const float*)d_in[13];
    const float* bsp = (const float*)d_in[14];
    float* out = (float*)d_out;

    int N = in_sizes[0] / 5;
    if (N > NMAXV) N = NMAXV;
    int U = in_sizes[2];
    if (U > MAXU) U = MAXU;

    void* cnt_ptr = nullptr;
    cudaGetSymbolAddress(&cnt_ptr, g_cnt);
    cudaMemsetAsync(cnt_ptr, 0, (size_t)U * sizeof(int));

    scatter_kernel<<<(N + 255) / 256, 256>>>(unq_inv, coords, N);
    xemp_kernel<<<1, 64>>>(b1, W2, b2);
    mlp_kernel<<<(N + 127) / 128, 128>>>(vf, W1, b1, W2, b2, N);
    pillar_kernel<<<(U + 127) / 128, 128>>>(unq_cnt, Wc1, bc1, Wc2, bc2,
                                            Wsp, bsp, out, U);

    long long feat = (long long)U * 64;
    if ((long long)out_size > feat) {
        long long extra = (long long)out_size - feat;
        int n = (extra > U) ? U : (int)extra;
        mask_kernel<<<(n + 255) / 256, 256>>>(unq_cnt, out, feat, n);
    }
}

// round 5
// speedup vs baseline: 1.9428x; 1.2605x over previous
#include <cuda_runtime.h>
#include <cstdint>

#define NUM_BINS 32
#define MAXK     4
#define MAXU     100352
#define NMAXV    (2*MAXU)
#define NPAD     (NMAXV + 64)

typedef unsigned long long u64;

__device__ int   g_cnt[MAXU];
__device__ int4  g_list[MAXU];                   // packed (voxel<<5 | bin)
__device__ float g_xT[(size_t)64 * NPAD];        // transposed MLP output [c][v]
__device__ float g_xemp[64];                     // MLP(0) vector

// ---------------- packed f32x2 helpers -------------------------------------
__device__ __forceinline__ u64 pk2(float lo, float hi) {
    u64 r; asm("mov.b64 %0,{%1,%2};" : "=l"(r) : "f"(lo), "f"(hi)); return r;
}
__device__ __forceinline__ u64 dup2(float v) { return pk2(v, v); }
__device__ __forceinline__ void fma2(u64 &d, u64 a, u64 b) {
    asm("fma.rn.f32x2 %0,%1,%2,%0;" : "+l"(d) : "l"(a), "l"(b));
}
__device__ __forceinline__ float2 unpk(u64 v) {
    float2 r; asm("mov.b64 {%0,%1},%2;" : "=f"(r.x), "=f"(r.y) : "l"(v)); return r;
}
union F4U { float4 f; u64 u[2]; };

__device__ __forceinline__ float sigm(float x) {
    return __fdividef(1.f, 1.f + __expf(-x));
}

// ---------------------------------------------------------------- scatter ---
__global__ void scatter_kernel(const int* __restrict__ unq_inv,
                               const int* __restrict__ coords, int N) {
    int i = blockIdx.x * blockDim.x + threadIdx.x;
    if (i >= N) return;
    int p = unq_inv[i];
    int b = coords[4 * i + 1];
    int k = atomicAdd(&g_cnt[p], 1);
    if (k < MAXK) ((int*)g_list)[p * 4 + k] = (i << 5) | (b & 31);
}

// ------------------------------------------------------------------- mask ---
__global__ void mask_kernel(const int* __restrict__ cnt, float* __restrict__ out,
                            long long base, int n) {
    int i = blockIdx.x * blockDim.x + threadIdx.x;
    if (i < n) out[base + i] = (cnt[i] >= 2) ? 1.0f : 0.0f;
}

// ------------------------------------------------------------------- xemp ---
__global__ void xemp_kernel(const float* __restrict__ b1,
                            const float* __restrict__ W2,
                            const float* __restrict__ b2) {
    int c = threadIdx.x;   // 64 threads
    float acc = b2[c];
#pragma unroll
    for (int j = 0; j < 32; j++)
        acc = fmaf(fmaxf(b1[j], 0.f), W2[j * 64 + c], acc);
    g_xemp[c] = acc;
}

// ---------------------------------------------------- kernel A: MLP (tiled) --
// Tile = 64 voxels, 256 threads.
// Phase A: 4 threads/voxel compute hidden (32) into h_sh[j][v].
// Phase B: thread = (channel-pair cp, 8-voxel slot); W2 column-pair in regs,
//          h streamed via broadcast LDS.128 -> 1 LDS : 4 fma2.
// Writeout: smem transpose -> coalesced STG to g_xT[c][v].
__global__ __launch_bounds__(256, 2)
void mlp2_kernel(const float* __restrict__ vf,
                 const float* __restrict__ W1, const float* __restrict__ b1,
                 const float* __restrict__ W2, const float* __restrict__ b2,
                 int N) {
    __shared__ __align__(16) float W1s[5][32];
    __shared__ __align__(16) float b1s[32];
    __shared__ __align__(16) float h_sh[32][68];
    __shared__ __align__(16) float x_sh[64][65];

    const int tid  = threadIdx.x;
    const int cp   = tid & 31;        // channels (2cp, 2cp+1)
    const int slot = tid >> 5;        // 0..7 -> voxels slot*8 .. +7
    const int v0   = blockIdx.x * 64;

    // W2 column-pair -> registers (coalesced across lanes)
    u64 wp[32];
#pragma unroll
    for (int j = 0; j < 32; j++) wp[j] = *(const u64*)&W2[j * 64 + 2 * cp];
    const float2 b2p = *(const float2*)&b2[2 * cp];

    for (int i = tid; i < 160; i += 256) W1s[i / 32][i % 32] = W1[i];
    if (tid < 32) b1s[tid] = b1[tid];
    __syncthreads();

    // ---- phase A: hidden ----
    {
        int v = tid & 63, qr = tid >> 6;       // qr: j range qr*8..qr*8+7
        int gv = v0 + v;
        float f[5];
        bool ok = gv < N;
#pragma unroll
        for (int i = 0; i < 5; i++) f[i] = ok ? vf[(size_t)gv * 5 + i] : 0.f;
        u64 acc[4];
#pragma unroll
        for (int t = 0; t < 4; t++) acc[t] = *(const u64*)&b1s[qr * 8 + 2 * t];
#pragma unroll
        for (int i = 0; i < 5; i++) {
            u64 fd = dup2(f[i]);
#pragma unroll
            for (int t = 0; t < 4; t++)
                fma2(acc[t], fd, *(const u64*)&W1s[i][qr * 8 + 2 * t]);
        }
#pragma unroll
        for (int t = 0; t < 4; t++) {
            float2 h = unpk(acc[t]);
            h_sh[qr * 8 + 2 * t][v]     = fmaxf(h.x, 0.f);
            h_sh[qr * 8 + 2 * t + 1][v] = fmaxf(h.y, 0.f);
        }
    }
    __syncthreads();

    // ---- phase B: layer 2 ----
    {
        const int vb = slot * 8;
        u64 accA[4], accB[4];
#pragma unroll
        for (int t = 0; t < 4; t++) { accA[t] = dup2(b2p.x); accB[t] = dup2(b2p.y); }
#pragma unroll
        for (int j = 0; j < 32; j++) {
            F4U A, B;
            A.f = *(const float4*)&h_sh[j][vb];
            B.f = *(const float4*)&h_sh[j][vb + 4];
            float2 w = unpk(wp[j]);
            u64 d0 = dup2(w.x), d1 = dup2(w.y);
            fma2(accA[0], A.u[0], d0); fma2(accA[1], A.u[1], d0);
            fma2(accA[2], B.u[0], d0); fma2(accA[3], B.u[1], d0);
            fma2(accB[0], A.u[0], d1); fma2(accB[1], A.u[1], d1);
            fma2(accB[2], B.u[0], d1); fma2(accB[3], B.u[1], d1);
        }
#pragma unroll
        for (int t = 0; t < 4; t++) {
            float2 a = unpk(accA[t]);
            float2 b = unpk(accB[t]);
            x_sh[vb + 2 * t][2 * cp]         = a.x;
            x_sh[vb + 2 * t + 1][2 * cp]     = a.y;
            x_sh[vb + 2 * t][2 * cp + 1]     = b.x;
            x_sh[vb + 2 * t + 1][2 * cp + 1] = b.y;
        }
    }
    __syncthreads();

    // ---- writeout: coalesced transposed store ----
    for (int idx = tid; idx < 64 * 64; idx += 256) {
        int c = idx >> 6, v = idx & 63;
        if (v0 + v < N) g_xT[(size_t)c * NPAD + v0 + v] = x_sh[v][c];
    }
}

// -------------------------------------------------- kernel B: attention -----
// thread = pillar; x loads from transposed g_xT (coalesced across lanes);
// weights broadcast from smem; att + output staged in smem; coalesced out.
__global__ __launch_bounds__(128, 3)
void pillar2_kernel(const int* __restrict__ unq_cnt,
                    const float* __restrict__ Wc1, const float* __restrict__ bc1,
                    const float* __restrict__ Wc2, const float* __restrict__ bc2,
                    const float* __restrict__ Wsp, const float* __restrict__ bsp,
                    float* __restrict__ out, int U) {
    __shared__ __align__(16) float Wc1s[64 * 16];   // [c][j]
    __shared__ __align__(16) float Wc2s[16 * 64];   // [j][c]
    __shared__ __align__(16) float xemps[64];
    __shared__ float bc1s[16];
    __shared__ __align__(16) float bc22[64];        // 2*bc2
    __shared__ __align__(16) u64 ats[32][129];      // att / out staging

    const int tid = threadIdx.x;
    for (int i = tid; i < 1024; i += 128) { Wc1s[i] = Wc1[i]; Wc2s[i] = Wc2[i]; }
    if (tid < 64) { xemps[tid] = g_xemp[tid]; bc22[tid] = 2.f * bc2[tid]; }
    if (tid < 16) bc1s[tid] = bc1[tid];
    __syncthreads();

    const int p = blockIdx.x * 128 + tid;
    const bool active = p < U;

    const float NEG = __int_as_float(0xff800000);
    float wm[7], wx[7];
#pragma unroll
    for (int t = 0; t < 7; t++) { wm[t] = Wsp[t]; wx[t] = Wsp[7 + t]; }
    const float bspv = bsp[0];

    int K = 0;
    int4 e = make_int4(0, 0, 0, 0);
    if (active) {
        K = unq_cnt[p];
        K = (K < 0) ? 0 : ((K > MAXK) ? MAXK : K);
        e = g_list[p];
    }
    int vs_[4] = { e.x >> 5, e.y >> 5, e.z >> 5, e.w >> 5 };
    int bs_[4] = { e.x & 31, e.y & 31, e.z & 31, e.w & 31 };
#pragma unroll
    for (int k = 0; k < 4; k++) if (k >= K) bs_[k] = -1;
    const float fK = (float)(NUM_BINS - K);

    // ---- phase 1: avg/max per channel -> catt hidden partials -------------
    u64 ap[8], aq[8];
#pragma unroll
    for (int j = 0; j < 8; j++) { ap[j] = 0ull; aq[j] = 0ull; }

    for (int c = 0; c < 64; c++) {
        float xe = xemps[c];
        float s = 0.f, mx = xe;
        const float* xr = &g_xT[(size_t)c * NPAD];
#pragma unroll
        for (int k = 0; k < 4; k++) if (k < K) {
            float xv = xr[vs_[k]];
            s += xv; mx = fmaxf(mx, xv);
        }
        float av = (s + fK * xe) * 0.03125f;
        u64 ad = dup2(av), md = dup2(mx);
        const u64* wr = (const u64*)&Wc1s[c * 16];
#pragma unroll
        for (int jp = 0; jp < 8; jp++) {
            u64 w = wr[jp];
            fma2(ap[jp], ad, w);
            fma2(aq[jp], md, w);
        }
    }

    // ---- catt gate vector g[16] packed dups ------------------------------
    u64 gd[16];
#pragma unroll
    for (int jp = 0; jp < 8; jp++) {
        float2 pp = unpk(ap[jp]);
        float2 qq = unpk(aq[jp]);
        float g0 = fmaxf(pp.x + bc1s[2 * jp], 0.f)     + fmaxf(qq.x + bc1s[2 * jp], 0.f);
        float g1 = fmaxf(pp.y + bc1s[2 * jp + 1], 0.f) + fmaxf(qq.y + bc1s[2 * jp + 1], 0.f);
        gd[2 * jp]     = dup2(g0);
        gd[2 * jp + 1] = dup2(g1);
    }

    // ---- phase 2: channel attention + bin statistics ---------------------
    float ssum[4] = {0.f, 0.f, 0.f, 0.f};
    float smax[4] = {NEG, NEG, NEG, NEG};
    float sesum = 0.f, semax = NEG;
#pragma unroll 4
    for (int q = 0; q < 32; q++) {
        u64 acc = *(const u64*)&bc22[2 * q];
#pragma unroll
        for (int j = 0; j < 16; j++)
            fma2(acc, gd[j], *(const u64*)&Wc2s[j * 64 + 2 * q]);
        float2 A = unpk(acc);
        float a0 = sigm(A.x), a1 = sigm(A.y);
        ats[q][tid] = pk2(a0, a1);
        float y0 = a0 * xemps[2 * q], y1 = a1 * xemps[2 * q + 1];
        sesum += y0 + y1;
        semax = fmaxf(semax, fmaxf(y0, y1));
        const float* x0r = &g_xT[(size_t)(2 * q) * NPAD];
        const float* x1r = &g_xT[(size_t)(2 * q + 1) * NPAD];
#pragma unroll
        for (int k = 0; k < 4; k++) if (k < K) {
            float z0 = a0 * x0r[vs_[k]];
            float z1 = a1 * x1r[vs_[k]];
            ssum[k] += z0 + z1;
            smax[k] = fmaxf(smax[k], fmaxf(z0, z1));
        }
    }

    // ---- bin attention: 7-tap conv over 32 bins, in registers ------------
    const float se_m = sesum * (1.f / 64.f);
    const float se_x = semax;
    float smv[4], sxv[4];
#pragma unroll
    for (int k = 0; k < 4; k++) { smv[k] = ssum[k] * (1.f / 64.f); sxv[k] = smax[k]; }

    float vmA[32], vxA[32];
#pragma unroll
    for (int i = 0; i < 32; i++) {
        float m = se_m, x = se_x;
#pragma unroll
        for (int k = 0; k < 4; k++) {
            bool h = (bs_[k] == i);
            m = h ? smv[k] : m;
            x = h ? sxv[k] : x;
        }
        vmA[i] = m; vxA[i] = x;
    }
    float emax = NEG, emin = -NEG;
    float argk[4] = {0.f, 0.f, 0.f, 0.f};
#pragma unroll
    for (int b = 0; b < 32; b++) {
        float a = bspv;
#pragma unroll
        for (int t = 0; t < 7; t++) {
            int i = b + t - 3;
            if (i >= 0 && i < 32) {
                a = fmaf(wm[t], vmA[i], a);
                a = fmaf(wx[t], vxA[i], a);
            }
        }
        bool occ = false;
#pragma unroll
        for (int k = 0; k < 4; k++) {
            bool h = (bs_[k] == b);
            argk[k] = h ? a : argk[k];
            occ = occ | h;
        }
        emax = occ ? emax : fmaxf(emax, a);
        emin = occ ? emin : fminf(emin, a);
    }
    float sigk[4];
#pragma unroll
    for (int k = 0; k < 4; k++) sigk[k] = sigm(argk[k]);
    const float sigeP = sigm(emax);    // y_empty >= 0
    const float sigeN = sigm(emin);    // y_empty <  0

    // ---- phase 3: final max over bins (overwrite staging with output) ----
#pragma unroll 4
    for (int q = 0; q < 32; q++) {
        float2 A = unpk(ats[q][tid]);
        float xe0 = xemps[2 * q], xe1 = xemps[2 * q + 1];
        float M0 = xe0 * ((xe0 >= 0.f) ? sigeP : sigeN);
        float M1 = xe1 * ((xe1 >= 0.f) ? sigeP : sigeN);
        const float* x0r = &g_xT[(size_t)(2 * q) * NPAD];
        const float* x1r = &g_xT[(size_t)(2 * q + 1) * NPAD];
#pragma unroll
        for (int k = 0; k < 4; k++) if (k < K) {
            M0 = fmaxf(M0, x0r[vs_[k]] * sigk[k]);
            M1 = fmaxf(M1, x1r[vs_[k]] * sigk[k]);
        }
        ats[q][tid] = pk2(A.x * M0, A.y * M1);
    }
    __syncthreads();

    // ---- coalesced writeout ---------------------------------------------
    const int pbase = blockIdx.x * 128;
    for (int idx = tid; idx < 128 * 64; idx += 128) {
        int pl = idx >> 6, c = idx & 63;
        if (pbase + pl < U) {
            const float* av = (const float*)&ats[c >> 1][pl];
            out[(size_t)(pbase + pl) * 64 + c] = av[c & 1];
        }
    }
}

// ------------------------------------------------------------------ launch --
extern "C" void kernel_launch(void* const* d_in, const int* in_sizes, int n_in,
                              void* d_out, int out_size) {
    const float* vf      = (const float*)d_in[0];
    const int*   coords  = (const int*)  d_in[1];
    const int*   unq_inv = (const int*)  d_in[3];
    const int*   unq_cnt = (const int*)  d_in[4];
    const float* W1  = (const float*)d_in[5];
    const float* b1  = (const float*)d_in[6];
    const float* W2  = (const float*)d_in[7];
    const float* b2  = (const float*)d_in[8];
    const float* Wc1 = (const float*)d_in[9];
    const float* bc1 = (const float*)d_in[10];
    const float* Wc2 = (const float*)d_in[11];
    const float* bc2 = (const float*)d_in[12];
    const float* Wsp = (const float*)d_in[13];
    const float* bsp = (const float*)d_in[14];
    float* out = (float*)d_out;

    int N = in_sizes[0] / 5;
    if (N > NMAXV) N = NMAXV;
    int U = in_sizes[2];
    if (U > MAXU) U = MAXU;

    void* cnt_ptr = nullptr;
    cudaGetSymbolAddress(&cnt_ptr, g_cnt);
    cudaMemsetAsync(cnt_ptr, 0, (size_t)U * sizeof(int));

    scatter_kernel<<<(N + 255) / 256, 256>>>(unq_inv, coords, N);
    xemp_kernel<<<1, 64>>>(b1, W2, b2);
    mlp2_kernel<<<(N + 63) / 64, 256>>>(vf, W1, b1, W2, b2, N);
    pillar2_kernel<<<(U + 127) / 128, 128>>>(unq_cnt, Wc1, bc1, Wc2, bc2,
                                             Wsp, bsp, out, U);

    long long feat = (long long)U * 64;
    if ((long long)out_size > feat) {
        long long extra = (long long)out_size - feat;
        int n = (extra > U) ? U : (int)extra;
        mask_kernel<<<(n + 255) / 256, 256>>>(unq_cnt, out, feat, n);
    }
}

// round 6
// speedup vs baseline: 2.0139x; 1.0366x over previous
#include <cuda_runtime.h>
#include <cstdint>

#define NUM_BINS 32
#define MAXK     4
#define MAXU     100352
#define NMAXV    (2*MAXU)
#define NPAD     (NMAXV + 64)

typedef unsigned long long u64;

__device__ int   g_cnt[MAXU];
__device__ int4  g_list[MAXU];                   // packed (voxel<<5 | bin)
__device__ float g_xT[(size_t)64 * NPAD];        // transposed MLP output [c][v]
__device__ float g_xemp[64];                     // MLP(0) vector

// ---------------- packed f32x2 helpers -------------------------------------
__device__ __forceinline__ u64 pk2(float lo, float hi) {
    u64 r; asm("mov.b64 %0,{%1,%2};" : "=l"(r) : "f"(lo), "f"(hi)); return r;
}
__device__ __forceinline__ u64 dup2(float v) { return pk2(v, v); }
__device__ __forceinline__ void fma2(u64 &d, u64 a, u64 b) {
    asm("fma.rn.f32x2 %0,%1,%2,%0;" : "+l"(d) : "l"(a), "l"(b));
}
__device__ __forceinline__ float2 unpk(u64 v) {
    float2 r; asm("mov.b64 {%0,%1},%2;" : "=f"(r.x), "=f"(r.y) : "l"(v)); return r;
}
union F4U { float4 f; u64 u[2]; };

__device__ __forceinline__ float sigm(float x) {
    return __fdividef(1.f, 1.f + __expf(-x));
}

// ---------------------------------------------------------------- scatter ---
__global__ void scatter_kernel(const int* __restrict__ unq_inv,
                               const int* __restrict__ coords, int N) {
    int i = blockIdx.x * blockDim.x + threadIdx.x;
    if (i >= N) return;
    int p = unq_inv[i];
    int b = coords[4 * i + 1];
    int k = atomicAdd(&g_cnt[p], 1);
    if (k < MAXK) ((int*)g_list)[p * 4 + k] = (i << 5) | (b & 31);
}

// ------------------------------------------------------------------- mask ---
__global__ void mask_kernel(const int* __restrict__ cnt, float* __restrict__ out,
                            long long base, int n) {
    int i = blockIdx.x * blockDim.x + threadIdx.x;
    if (i < n) out[base + i] = (cnt[i] >= 2) ? 1.0f : 0.0f;
}

// ------------------------------------------------------------------- xemp ---
__global__ void xemp_kernel(const float* __restrict__ b1,
                            const float* __restrict__ W2,
                            const float* __restrict__ b2) {
    int c = threadIdx.x;   // 64 threads
    float acc = b2[c];
#pragma unroll
    for (int j = 0; j < 32; j++)
        acc = fmaf(fmaxf(b1[j], 0.f), W2[j * 64 + c], acc);
    g_xemp[c] = acc;
}

// ---------------------------------------------------- kernel A: MLP (tiled) --
__global__ __launch_bounds__(256, 2)
void mlp2_kernel(const float* __restrict__ vf,
                 const float* __restrict__ W1, const float* __restrict__ b1,
                 const float* __restrict__ W2, const float* __restrict__ b2,
                 int N) {
    __shared__ __align__(16) float W1s[5][32];
    __shared__ __align__(16) float b1s[32];
    __shared__ __align__(16) float h_sh[32][68];
    __shared__ __align__(16) float x_sh[64][65];

    const int tid  = threadIdx.x;
    const int cp   = tid & 31;        // channels (2cp, 2cp+1)
    const int slot = tid >> 5;        // 0..7 -> voxels slot*8 .. +7
    const int v0   = blockIdx.x * 64;

    u64 wp[32];
#pragma unroll
    for (int j = 0; j < 32; j++) wp[j] = *(const u64*)&W2[j * 64 + 2 * cp];
    const float2 b2p = *(const float2*)&b2[2 * cp];

    for (int i = tid; i < 160; i += 256) W1s[i / 32][i % 32] = W1[i];
    if (tid < 32) b1s[tid] = b1[tid];
    __syncthreads();

    // ---- phase A: hidden ----
    {
        int v = tid & 63, qr = tid >> 6;
        int gv = v0 + v;
        float f[5];
        bool ok = gv < N;
#pragma unroll
        for (int i = 0; i < 5; i++) f[i] = ok ? vf[(size_t)gv * 5 + i] : 0.f;
        u64 acc[4];
#pragma unroll
        for (int t = 0; t < 4; t++) acc[t] = *(const u64*)&b1s[qr * 8 + 2 * t];
#pragma unroll
        for (int i = 0; i < 5; i++) {
            u64 fd = dup2(f[i]);
#pragma unroll
            for (int t = 0; t < 4; t++)
                fma2(acc[t], fd, *(const u64*)&W1s[i][qr * 8 + 2 * t]);
        }
#pragma unroll
        for (int t = 0; t < 4; t++) {
            float2 h = unpk(acc[t]);
            h_sh[qr * 8 + 2 * t][v]     = fmaxf(h.x, 0.f);
            h_sh[qr * 8 + 2 * t + 1][v] = fmaxf(h.y, 0.f);
        }
    }
    __syncthreads();

    // ---- phase B: layer 2 ----
    {
        const int vb = slot * 8;
        u64 accA[4], accB[4];
#pragma unroll
        for (int t = 0; t < 4; t++) { accA[t] = dup2(b2p.x); accB[t] = dup2(b2p.y); }
#pragma unroll
        for (int j = 0; j < 32; j++) {
            F4U A, B;
            A.f = *(const float4*)&h_sh[j][vb];
            B.f = *(const float4*)&h_sh[j][vb + 4];
            float2 w = unpk(wp[j]);
            u64 d0 = dup2(w.x), d1 = dup2(w.y);
            fma2(accA[0], A.u[0], d0); fma2(accA[1], A.u[1], d0);
            fma2(accA[2], B.u[0], d0); fma2(accA[3], B.u[1], d0);
            fma2(accB[0], A.u[0], d1); fma2(accB[1], A.u[1], d1);
            fma2(accB[2], B.u[0], d1); fma2(accB[3], B.u[1], d1);
        }
#pragma unroll
        for (int t = 0; t < 4; t++) {
            float2 a = unpk(accA[t]);
            float2 b = unpk(accB[t]);
            x_sh[vb + 2 * t][2 * cp]         = a.x;
            x_sh[vb + 2 * t + 1][2 * cp]     = a.y;
            x_sh[vb + 2 * t][2 * cp + 1]     = b.x;
            x_sh[vb + 2 * t + 1][2 * cp + 1] = b.y;
        }
    }
    __syncthreads();

    for (int idx = tid; idx < 64 * 64; idx += 256) {
        int c = idx >> 6, v = idx & 63;
        if (v0 + v < N) g_xT[(size_t)c * NPAD + v0 + v] = x_sh[v][c];
    }
}

// -------------------------------------------------- kernel B: attention -----
// thread = pillar; LDS.128 weight streams; sparse-correction conv (no big
// register arrays); output staged in two 32-channel halves; att recomputed.
__global__ __launch_bounds__(128, 5)
void pillar3_kernel(const int* __restrict__ unq_cnt,
                    const float* __restrict__ Wc1, const float* __restrict__ bc1,
                    const float* __restrict__ Wc2, const float* __restrict__ bc2,
                    const float* __restrict__ Wsp, const float* __restrict__ bsp,
                    float* __restrict__ out, int U) {
    __shared__ __align__(16) float Wc1s[64 * 16];   // [c][j], rows 64B
    __shared__ __align__(16) u64   Wc2P[32 * 16];   // [q][j] packed ch-pairs
    __shared__ __align__(16) float xemps[64];
    __shared__ float bc1s[16];
    __shared__ __align__(16) u64   bc22p[32];       // 2*bc2 packed pairs
    __shared__ __align__(16) u64   Amx[32];         // conv bg coeffs per bin
    __shared__ __align__(16) u64   wmx[8];          // packed (wm[t], wx[t])
    __shared__ __align__(16) u64   oh[16][131];     // half-output staging

    const int tid = threadIdx.x;
    for (int i = tid; i < 1024; i += 128) Wc1s[i] = Wc1[i];
    for (int i = tid; i < 512; i += 128) {
        int q = i >> 4, j = i & 15;
        Wc2P[q * 16 + j] = pk2(Wc2[j * 64 + 2 * q], Wc2[j * 64 + 2 * q + 1]);
    }
    if (tid < 64) xemps[tid] = g_xemp[tid];
    if (tid < 32) bc22p[tid] = pk2(2.f * bc2[2 * tid], 2.f * bc2[2 * tid + 1]);
    if (tid < 16) bc1s[tid] = bc1[tid];
    if (tid < 7)  wmx[tid] = pk2(Wsp[tid], Wsp[7 + tid]);
    if (tid < 32) {
        float am = 0.f, ax = 0.f;
#pragma unroll
        for (int t = 0; t < 7; t++) {
            int i2 = tid + t - 3;
            if (i2 >= 0 && i2 < 32) { am += Wsp[t]; ax += Wsp[7 + t]; }
        }
        Amx[tid] = pk2(am, ax);
    }
    __syncthreads();

    const float bspv = bsp[0];
    const float NEG = __int_as_float(0xff800000);
    const int pbase = blockIdx.x * 128;
    const int p = pbase + tid;
    const bool active = p < U;

    int K = 0;
    int4 e = make_int4(0, 0, 0, 0);
    if (active) {
        K = unq_cnt[p];
        K = (K < 0) ? 0 : ((K > MAXK) ? MAXK : K);
        e = g_list[p];
    }
    int vs_[4] = { e.x >> 5, e.y >> 5, e.z >> 5, e.w >> 5 };
    int bs_[4] = { e.x & 31, e.y & 31, e.z & 31, e.w & 31 };
#pragma unroll
    for (int k = 0; k < 4; k++) if (k >= K) { bs_[k] = -1000; vs_[k] = 0; }
    const float fK = (float)(NUM_BINS - K);

    // ---- phase 1: avg/max per channel -> catt hidden partials -------------
    u64 ap[8], aq[8];
#pragma unroll
    for (int j = 0; j < 8; j++) { ap[j] = 0ull; aq[j] = 0ull; }
    {
        const float* xc = g_xT;
#pragma unroll 4
        for (int c = 0; c < 64; c++) {
            float xe = xemps[c];
            float s = 0.f, mx = xe;
#pragma unroll
            for (int k = 0; k < 4; k++) if (k < K) {
                float xv = xc[vs_[k]];
                s += xv; mx = fmaxf(mx, xv);
            }
            float av = (s + fK * xe) * 0.03125f;
            u64 ad = dup2(av), md = dup2(mx);
            const ulonglong2* wr = (const ulonglong2*)&Wc1s[c * 16];
#pragma unroll
            for (int h = 0; h < 4; h++) {
                ulonglong2 w = wr[h];
                fma2(ap[2 * h],     ad, w.x);
                fma2(ap[2 * h + 1], ad, w.y);
                fma2(aq[2 * h],     md, w.x);
                fma2(aq[2 * h + 1], md, w.y);
            }
            xc += NPAD;
        }
    }

    // ---- catt gate vector, packed dups -----------------------------------
    u64 gd[16];
#pragma unroll
    for (int jp = 0; jp < 8; jp++) {
        float2 pp = unpk(ap[jp]);
        float2 qq = unpk(aq[jp]);
        float g0 = fmaxf(pp.x + bc1s[2 * jp], 0.f)     + fmaxf(qq.x + bc1s[2 * jp], 0.f);
        float g1 = fmaxf(pp.y + bc1s[2 * jp + 1], 0.f) + fmaxf(qq.y + bc1s[2 * jp + 1], 0.f);
        gd[2 * jp]     = dup2(g0);
        gd[2 * jp + 1] = dup2(g1);
    }

    // ---- phase 2: channel attention + bin statistics ---------------------
    float ssum[4] = {0.f, 0.f, 0.f, 0.f};
    float smax4[4] = {NEG, NEG, NEG, NEG};
    float sesum = 0.f, semax = NEG;
    {
        const float* x0 = g_xT;
        const float* x1 = g_xT + NPAD;
#pragma unroll 2
        for (int q = 0; q < 32; q++) {
            u64 acc = bc22p[q];
            const ulonglong2* w2 = (const ulonglong2*)&Wc2P[q * 16];
#pragma unroll
            for (int h = 0; h < 8; h++) {
                ulonglong2 w = w2[h];
                fma2(acc, gd[2 * h],     w.x);
                fma2(acc, gd[2 * h + 1], w.y);
            }
            float2 A = unpk(acc);
            float a0 = sigm(A.x), a1 = sigm(A.y);
            float y0 = a0 * xemps[2 * q], y1 = a1 * xemps[2 * q + 1];
            sesum += y0 + y1;
            semax = fmaxf(semax, fmaxf(y0, y1));
#pragma unroll
            for (int k = 0; k < 4; k++) if (k < K) {
                float z0 = a0 * x0[vs_[k]];
                float z1 = a1 * x1[vs_[k]];
                ssum[k] += z0 + z1;
                smax4[k] = fmaxf(smax4[k], fmaxf(z0, z1));
            }
            x0 += 2 * NPAD;
            x1 += 2 * NPAD;
        }
    }

    // ---- bin attention: bg + sparse corrections --------------------------
    const float se_m = sesum * (1.f / 64.f);
    const float se_x = semax;
    const u64 semx = pk2(se_m, se_x);
    u64 dk2[4];
#pragma unroll
    for (int k = 0; k < 4; k++)
        dk2[k] = pk2(ssum[k] * (1.f / 64.f) - se_m, smax4[k] - se_x);

    float argk[4] = {0.f, 0.f, 0.f, 0.f};
    float emax = NEG, emin = -NEG;
#pragma unroll
    for (int b = 0; b < 32; b++) {
        u64 a2 = pk2(bspv, 0.f);
        fma2(a2, semx, Amx[b]);
        bool occ = false;
        bool hit[4];
#pragma unroll
        for (int k = 0; k < 4; k++) {
            int d = bs_[k] - b;
            if ((unsigned)(d + 3) <= 6u) fma2(a2, dk2[k], wmx[d + 3]);
            hit[k] = (d == 0);
            occ |= hit[k];
        }
        float2 av = unpk(a2);
        float a = av.x + av.y;
#pragma unroll
        for (int k = 0; k < 4; k++) argk[k] = hit[k] ? a : argk[k];
        emax = occ ? emax : fmaxf(emax, a);
        emin = occ ? emin : fminf(emin, a);
    }
    float sigk[4];
#pragma unroll
    for (int k = 0; k < 4; k++) sigk[k] = sigm(argk[k]);
    const float sigeP = sigm(emax);    // y_empty >= 0
    const float sigeN = sigm(emin);    // y_empty <  0

    // ---- phase 3: final max over bins, in two 32-channel halves ----------
#pragma unroll
    for (int half = 0; half < 2; half++) {
        const float* x0 = g_xT + (size_t)(half * 32) * NPAD;
        const float* x1 = x0 + NPAD;
#pragma unroll 2
        for (int qq = 0; qq < 16; qq++) {
            int q = half * 16 + qq;
            u64 acc = bc22p[q];
            const ulonglong2* w2 = (const ulonglong2*)&Wc2P[q * 16];
#pragma unroll
            for (int h = 0; h < 8; h++) {
                ulonglong2 w = w2[h];
                fma2(acc, gd[2 * h],     w.x);
                fma2(acc, gd[2 * h + 1], w.y);
            }
            float2 A = unpk(acc);
            float a0 = sigm(A.x), a1 = sigm(A.y);
            float xe0 = xemps[2 * q], xe1 = xemps[2 * q + 1];
            float M0 = xe0 * ((xe0 >= 0.f) ? sigeP : sigeN);
            float M1 = xe1 * ((xe1 >= 0.f) ? sigeP : sigeN);
#pragma unroll
            for (int k = 0; k < 4; k++) if (k < K) {
                M0 = fmaxf(M0, x0[vs_[k]] * sigk[k]);
                M1 = fmaxf(M1, x1[vs_[k]] * sigk[k]);
            }
            oh[qq][tid] = pk2(a0 * M0, a1 * M1);
            x0 += 2 * NPAD;
            x1 += 2 * NPAD;
        }
        __syncthreads();
        for (int idx = tid; idx < 128 * 32; idx += 128) {
            int pl = idx >> 5, c2 = idx & 31;
            int pg = pbase + pl;
            if (pg < U)
                out[(size_t)pg * 64 + half * 32 + c2] =
                    ((const float*)&oh[c2 >> 1][pl])[c2 & 1];
        }
        __syncthreads();
    }
}

// ------------------------------------------------------------------ launch --
extern "C" void kernel_launch(void* const* d_in, const int* in_sizes, int n_in,
                              void* d_out, int out_size) {
    const float* vf      = (const float*)d_in[0];
    const int*   coords  = (const int*)  d_in[1];
    const int*   unq_inv = (const int*)  d_in[3];
    const int*   unq_cnt = (const int*)  d_in[4];
    const float* W1  = (const float*)d_in[5];
    const float* b1  = (const float*)d_in[6];
    const float* W2  = (const float*)d_in[7];
    const float* b2  = (const float*)d_in[8];
    const float* Wc1 = (const float*)d_in[9];
    const float* bc1 = (const float*)d_in[10];
    const float* Wc2 = (const float*)d_in[11];
    const float* bc2 = (const float*)d_in[12];
    const float* Wsp = (const float*)d_in[13];
    const float* bsp = (const float*)d_in[14];
    float* out = (float*)d_out;

    int N = in_sizes[0] / 5;
    if (N > NMAXV) N = NMAXV;
    int U = in_sizes[2];
    if (U > MAXU) U = MAXU;

    void* cnt_ptr = nullptr;
    cudaGetSymbolAddress(&cnt_ptr, g_cnt);
    cudaMemsetAsync(cnt_ptr, 0, (size_t)U * sizeof(int));

    scatter_kernel<<<(N + 255) / 256, 256>>>(unq_inv, coords, N);
    xemp_kernel<<<1, 64>>>(b1, W2, b2);
    mlp2_kernel<<<(N + 63) / 64, 256>>>(vf, W1, b1, W2, b2, N);
    pillar3_kernel<<<(U + 127) / 128, 128>>>(unq_cnt, Wc1, bc1, Wc2, bc2,
                                             Wsp, bsp, out, U);

    long long feat = (long long)U * 64;
    if ((long long)out_size > feat) {
        long long extra = (long long)out_size - feat;
        int n = (extra > U) ? U : (int)extra;
        mask_kernel<<<(n + 255) / 256, 256>>>(unq_cnt, out, feat, n);
    }
}